// round 5
// baseline (speedup 1.0000x reference)
#include <cuda_runtime.h>
#include <cuda_fp16.h>
#include <math.h>
#include <stdint.h>

#define NF   48
#define NM   51
#define IMG  256
#define NB   16
#define TABN 2049
#define XS   80   // xs half stride
#define AS   72   // a half stride
#define WPF  56   // padded words per filter (7 rows x 8)

// ---- device scratch ----
__device__ __align__(16) uint32_t g_wb[NF * WPF];   // half2-broadcast weights [f][p*8+q]
__device__ __align__(16) uint32_t g_wbr[NF * WPF];  // doubly-reversed broadcast weights
__device__ float2 g_tab[NF * TABN];
__device__ float  g_r[NB * IMG * IMG];
__device__ float  g_partial[NB * 16];
__device__ float  g_scale[NB];

__device__ __forceinline__ half2 u2h(uint32_t u) { return *reinterpret_cast<half2*>(&u); }

// ---------------- K1: normalize weights, build half2 broadcast tables ----------------
__global__ void prep_kernel(const float* __restrict__ cw, const float* __restrict__ sf) {
    int f = threadIdx.x;
    if (f >= NF) return;
    float wn[49];
    float mean = 0.f;
    #pragma unroll
    for (int i = 0; i < 49; i++) mean += cw[f * 49 + i];
    mean *= (1.f / 49.f);
    float ss = 0.f;
    #pragma unroll
    for (int i = 0; i < 49; i++) { float d = cw[f * 49 + i] - mean; ss += d * d; }
    float s = sf[f] / (sqrtf(ss) + 1e-12f);
    #pragma unroll
    for (int i = 0; i < 49; i++) wn[i] = (cw[f * 49 + i] - mean) * s;
    #pragma unroll
    for (int p = 0; p < 7; p++) {
        #pragma unroll
        for (int q = 0; q < 7; q++) {
            uint32_t h  = (uint32_t)__half_as_ushort(__float2half(wn[p * 7 + q]));
            uint32_t hr = (uint32_t)__half_as_ushort(__float2half(wn[(6 - p) * 7 + (6 - q)]));
            g_wb[f * WPF + p * 8 + q]  = h | (h << 16);
            g_wbr[f * WPF + p * 8 + q] = hr | (hr << 16);
        }
        g_wb[f * WPF + p * 8 + 7]  = 0;
        g_wbr[f * WPF + p * 8 + 7] = 0;
    }
}

// ---------------- K2: RBF lookup table ----------------
__global__ void table_kernel(const float* __restrict__ rbw, const float* __restrict__ rbc) {
    __shared__ float wsh[NM], csh[NM];
    __shared__ float tsh[TABN];
    int f = blockIdx.x, tid = threadIdx.x;
    if (tid < NM) { wsh[tid] = rbw[f * NM + tid]; csh[tid] = rbc[tid]; }
    __syncthreads();
    for (int k = tid; k < TABN; k += blockDim.x) {
        float z = -16.f + (float)k * (1.f / 64.f);
        float acc = 0.f;
        #pragma unroll
        for (int m = 0; m < NM; m++) {
            float d = z - csh[m];
            acc += wsh[m] * __expf(-0.01f * d * d);
        }
        tsh[k] = acc;
    }
    __syncthreads();
    for (int k = tid; k < TABN; k += blockDim.x) {
        float v = tsh[k];
        float dl = (k < TABN - 1) ? (tsh[k + 1] - v) : 0.f;
        g_tab[f * TABN + k] = make_float2(v, dl);
    }
}

// ---------------- K3: fused conv -> RBF -> conv^T -> residual (HFMA2, smem weights) ----------------
__global__ void __launch_bounds__(256, 2)
main_kernel(const float* __restrict__ input, const float* __restrict__ net_input) {
    __shared__ __align__(16) half xs[76 * XS];
    __shared__ __align__(16) half as_h[70 * AS];
    __shared__ __align__(16) uint32_t s_wb[NF * WPF];
    __shared__ __align__(16) uint32_t s_wbr[NF * WPF];
    __shared__ float red[8];

    int blk  = blockIdx.x;
    int b    = blk >> 4;
    int tile = blk & 15;
    int ty0  = (tile >> 2) << 6;
    int tx0  = (tile & 3) << 6;
    int tid  = threadIdx.x;

    const float* ibase = input + b * IMG * IMG;

    // stage weight tables into smem (one-time)
    for (int i = tid; i < NF * WPF; i += 256) {
        s_wb[i]  = g_wb[i];
        s_wbr[i] = g_wbr[i];
    }

    // load x halo (76 rows x 78 cols used) with symmetric reflection -> fp16
    for (int idx = tid; idx < 76 * XS; idx += 256) {
        int ri = idx / XS, ci = idx - ri * XS;
        float v = 0.f;
        if (ci < 78) {
            int gy = ty0 + ri - 6, gx = tx0 + ci - 6;
            gy = (gy < 0) ? (-1 - gy) : ((gy >= IMG) ? (2 * IMG - 1 - gy) : gy);
            gx = (gx < 0) ? (-1 - gx) : ((gx >= IMG) ? (2 * IMG - 1 - gx) : gx);
            v = ibase[gy * IMG + gx];
        }
        xs[ri * XS + ci] = __float2half(v);
    }

    bool actA = tid < 252;
    int rg = tid / 18, cg = tid - rg * 18;
    int r0 = -3 + 5 * rg;
    int c0 = -3 + 4 * cg;

    int tyq = tid >> 4, txq = tid & 15;
    int ob = tyq << 2, oc = txq << 2;

    float oacc[16];
    #pragma unroll
    for (int i = 0; i < 16; i++) oacc[i] = 0.f;

    __syncthreads();

    #pragma unroll 1
    for (int f = 0; f < NF; f++) {
        // ---- phase A: forward conv (half2) + RBF ----
        float aout[20];
        if (actA) {
            const uint32_t* wf = s_wb + f * WPF;
            half2 za[10];
            #pragma unroll
            for (int i = 0; i < 10; i++) za[i] = __float2half2_rn(0.f);

            #pragma unroll
            for (int wr = 0; wr < 11; wr++) {
                const half* xp = xs + (r0 + 3 + wr) * XS + 4 * cg;
                half2 P[5], O[4];
                #pragma unroll
                for (int k = 0; k < 5; k++) P[k] = *(const half2*)(xp + 2 * k);
                #pragma unroll
                for (int k = 0; k < 4; k++)
                    O[k] = __halves2half2(__high2half(P[k]), __low2half(P[k + 1]));
                #pragma unroll
                for (int i = 0; i < 5; i++) {
                    int p = wr - i;
                    if (p >= 0 && p < 7) {
                        const uint32_t* w = wf + p * 8;   // smem broadcast
                        half2 w0 = u2h(w[0]), w1 = u2h(w[1]), w2 = u2h(w[2]),
                              w3 = u2h(w[3]), w4 = u2h(w[4]), w5 = u2h(w[5]), w6 = u2h(w[6]);
                        half2 a0 = za[i * 2], a1 = za[i * 2 + 1];
                        a0 = __hfma2(w0, P[0], a0);  a1 = __hfma2(w0, P[1], a1);
                        a0 = __hfma2(w1, O[0], a0);  a1 = __hfma2(w1, O[1], a1);
                        a0 = __hfma2(w2, P[1], a0);  a1 = __hfma2(w2, P[2], a1);
                        a0 = __hfma2(w3, O[1], a0);  a1 = __hfma2(w3, O[2], a1);
                        a0 = __hfma2(w4, P[2], a0);  a1 = __hfma2(w4, P[3], a1);
                        a0 = __hfma2(w5, O[2], a0);  a1 = __hfma2(w5, O[3], a1);
                        a0 = __hfma2(w6, P[3], a0);  a1 = __hfma2(w6, P[4], a1);
                        za[i * 2] = a0; za[i * 2 + 1] = a1;
                    }
                }
            }
            const float2* tb = g_tab + f * TABN;
            #pragma unroll
            for (int i = 0; i < 5; i++) {
                int gr = ty0 + r0 + i;
                bool rok = (gr >= 0) && (gr < IMG);
                float2 zl = __half22float2(za[i * 2]);
                float2 zh = __half22float2(za[i * 2 + 1]);
                float zv[4] = {zl.x, zl.y, zh.x, zh.y};
                #pragma unroll
                for (int j = 0; j < 4; j++) {
                    float t = (zv[j] + 16.f) * 64.f;
                    t = fminf(fmaxf(t, 0.f), 2047.99f);
                    int ix = (int)t;
                    float fr = t - (float)ix;
                    float2 tv = __ldg(tb + ix);
                    float a = tv.x + fr * tv.y;
                    int gc = tx0 + c0 + j;
                    if (!rok || gc < 0 || gc >= IMG) a = 0.f;
                    aout[i * 4 + j] = a;
                }
            }
        }
        __syncthreads();
        if (actA) {
            #pragma unroll
            for (int i = 0; i < 5; i++) {
                half* dst = as_h + (r0 + i + 3) * AS + 4 * cg;
                *(half2*)dst       = __floats2half2_rn(aout[i * 4], aout[i * 4 + 1]);
                *(half2*)(dst + 2) = __floats2half2_rn(aout[i * 4 + 2], aout[i * 4 + 3]);
            }
        }
        __syncthreads();

        // ---- phase B: conv^T (reversed weights, half2, per-filter fp32 fold) ----
        {
            const uint32_t* wf = s_wbr + f * WPF;
            half2 ga[8];
            #pragma unroll
            for (int i = 0; i < 8; i++) ga[i] = __float2half2_rn(0.f);

            #pragma unroll
            for (int wrb = 0; wrb < 10; wrb++) {
                const half* ap = as_h + (ob + wrb) * AS + oc;
                half2 P[5], O[4];
                #pragma unroll
                for (int k = 0; k < 5; k++) P[k] = *(const half2*)(ap + 2 * k);
                #pragma unroll
                for (int k = 0; k < 4; k++)
                    O[k] = __halves2half2(__high2half(P[k]), __low2half(P[k + 1]));
                #pragma unroll
                for (int i = 0; i < 4; i++) {
                    int p = wrb - i;
                    if (p >= 0 && p < 7) {
                        const uint32_t* w = wf + p * 8;   // smem broadcast
                        half2 w0 = u2h(w[0]), w1 = u2h(w[1]), w2 = u2h(w[2]),
                              w3 = u2h(w[3]), w4 = u2h(w[4]), w5 = u2h(w[5]), w6 = u2h(w[6]);
                        half2 a0 = ga[i * 2], a1 = ga[i * 2 + 1];
                        a0 = __hfma2(w0, P[0], a0);  a1 = __hfma2(w0, P[1], a1);
                        a0 = __hfma2(w1, O[0], a0);  a1 = __hfma2(w1, O[1], a1);
                        a0 = __hfma2(w2, P[1], a0);  a1 = __hfma2(w2, P[2], a1);
                        a0 = __hfma2(w3, O[1], a0);  a1 = __hfma2(w3, O[2], a1);
                        a0 = __hfma2(w4, P[2], a0);  a1 = __hfma2(w4, P[3], a1);
                        a0 = __hfma2(w5, O[2], a0);  a1 = __hfma2(w5, O[3], a1);
                        a0 = __hfma2(w6, P[3], a0);  a1 = __hfma2(w6, P[4], a1);
                        ga[i * 2] = a0; ga[i * 2 + 1] = a1;
                    }
                }
            }
            #pragma unroll
            for (int i = 0; i < 4; i++) {
                float2 lo = __half22float2(ga[i * 2]);
                float2 hi = __half22float2(ga[i * 2 + 1]);
                oacc[i * 4 + 0] += lo.x; oacc[i * 4 + 1] += lo.y;
                oacc[i * 4 + 2] += hi.x; oacc[i * 4 + 3] += hi.y;
            }
        }
    }

    // epilogue: r = input - convt - net_input ; per-block sum(r^2)
    const float* nbase = net_input + b * IMG * IMG;
    float* rbase = g_r + b * IMG * IMG;
    float ss = 0.f;
    #pragma unroll
    for (int i = 0; i < 4; i++) {
        int gy = ty0 + ob + i;
        int go = gy * IMG + tx0 + oc;
        float4 iv = *(const float4*)(ibase + go);
        float4 nv = *(const float4*)(nbase + go);
        float4 rv;
        rv.x = iv.x - oacc[i * 4 + 0] - nv.x;
        rv.y = iv.y - oacc[i * 4 + 1] - nv.y;
        rv.z = iv.z - oacc[i * 4 + 2] - nv.z;
        rv.w = iv.w - oacc[i * 4 + 3] - nv.w;
        *(float4*)(rbase + go) = rv;
        ss += rv.x * rv.x + rv.y * rv.y + rv.z * rv.z + rv.w * rv.w;
    }
    #pragma unroll
    for (int o = 16; o > 0; o >>= 1) ss += __shfl_down_sync(0xffffffffu, ss, o);
    if ((tid & 31) == 0) red[tid >> 5] = ss;
    __syncthreads();
    if (tid == 0) {
        float s = 0.f;
        #pragma unroll
        for (int w = 0; w < 8; w++) s += red[w];
        g_partial[blk] = s;
    }
}

// ---------------- K4a / K4b ----------------
__global__ void scale_kernel(const float* __restrict__ stdn, const float* __restrict__ alpha) {
    int b = blockIdx.x;
    if (threadIdx.x == 0) {
        float s = 0.f;
        #pragma unroll
        for (int t = 0; t < 16; t++) s += g_partial[b * 16 + t];
        float nr = sqrtf(s);
        float k = expf(alpha[0]) * stdn[b] * 256.f;
        g_scale[b] = fminf(1.f, k / (nr + 1e-12f));
    }
}

__global__ void final_kernel(const float* __restrict__ net_input, float* __restrict__ out) {
    int v = blockIdx.x * blockDim.x + threadIdx.x;
    if (v >= NB * IMG * IMG / 4) return;
    int b = v >> 14;
    float sc = g_scale[b];
    float4 rr = ((const float4*)g_r)[v];
    float4 nn = ((const float4*)net_input)[v];
    float4 o;
    o.x = nn.x + rr.x * sc;
    o.y = nn.y + rr.y * sc;
    o.z = nn.z + rr.z * sc;
    o.w = nn.w + rr.w * sc;
    ((float4*)out)[v] = o;
}

extern "C" void kernel_launch(void* const* d_in, const int* in_sizes, int n_in,
                              void* d_out, int out_size) {
    const float* input     = (const float*)d_in[0];
    const float* stdn      = (const float*)d_in[1];
    const float* net_input = (const float*)d_in[3];
    const float* cw        = (const float*)d_in[4];
    const float* sf        = (const float*)d_in[5];
    const float* alpha     = (const float*)d_in[6];
    const float* rbw       = (const float*)d_in[7];
    const float* rbc       = (const float*)d_in[8];
    float* out = (float*)d_out;

    prep_kernel<<<1, 64>>>(cw, sf);
    table_kernel<<<NF, 256>>>(rbw, rbc);
    main_kernel<<<256, 256>>>(input, net_input);
    scale_kernel<<<NB, 32>>>(stdn, alpha);
    final_kernel<<<1024, 256>>>(net_input, out);
}

// round 6
// speedup vs baseline: 1.9209x; 1.9209x over previous
#include <cuda_runtime.h>
#include <cuda_fp16.h>
#include <math.h>
#include <stdint.h>

#define NF   48
#define NM   51
#define IMG  256
#define NB   16
#define TABN 2049
#define XS   80   // xs half stride
#define AS   72   // a half stride

// ---- device scratch ----
__device__ __align__(16) uint32_t g_wb[NF * 52];   // half2-broadcast weights [f][p*7+q], pad->52
__device__ __align__(16) uint32_t g_wbr[NF * 52];  // doubly-reversed broadcast weights
__device__ float2 g_tab[NF * TABN];
__device__ float  g_r[NB * IMG * IMG];
__device__ float  g_partial[NB * 16];

__device__ __forceinline__ half2 u2h(uint32_t u) { return *reinterpret_cast<half2*>(&u); }

// ---------------- K1: normalize weights + broadcast tables + RBF table ----------------
__global__ void prep_table_kernel(const float* __restrict__ cw, const float* __restrict__ sf,
                                  const float* __restrict__ rbw, const float* __restrict__ rbc) {
    __shared__ float wn[49];
    __shared__ float msh[2];       // mean, scale
    __shared__ float wsh[NM], csh[NM];
    __shared__ float tsh[TABN];
    int f = blockIdx.x, tid = threadIdx.x;

    if (tid < 49) wn[tid] = cw[f * 49 + tid];
    if (tid < NM) { wsh[tid] = rbw[f * NM + tid]; csh[tid] = rbc[tid]; }
    __syncthreads();
    if (tid == 0) {
        float mean = 0.f;
        #pragma unroll
        for (int i = 0; i < 49; i++) mean += wn[i];
        mean *= (1.f / 49.f);
        float ss = 0.f;
        #pragma unroll
        for (int i = 0; i < 49; i++) { float d = wn[i] - mean; ss += d * d; }
        msh[0] = mean;
        msh[1] = sf[f] / (sqrtf(ss) + 1e-12f);
    }
    __syncthreads();
    if (tid < 49) wn[tid] = (wn[tid] - msh[0]) * msh[1];
    __syncthreads();
    if (tid < 49) {
        int p = tid / 7, q = tid - p * 7;
        uint32_t h  = (uint32_t)__half_as_ushort(__float2half(wn[p * 7 + q]));
        uint32_t hr = (uint32_t)__half_as_ushort(__float2half(wn[(6 - p) * 7 + (6 - q)]));
        g_wb[f * 52 + tid]  = h | (h << 16);
        g_wbr[f * 52 + tid] = hr | (hr << 16);
    } else if (tid < 52) {
        g_wb[f * 52 + tid] = 0; g_wbr[f * 52 + tid] = 0;
    }
    // RBF table
    for (int k = tid; k < TABN; k += blockDim.x) {
        float z = -16.f + (float)k * (1.f / 64.f);
        float acc = 0.f;
        #pragma unroll
        for (int m = 0; m < NM; m++) {
            float d = z - csh[m];
            acc += wsh[m] * __expf(-0.01f * d * d);
        }
        tsh[k] = acc;
    }
    __syncthreads();
    for (int k = tid; k < TABN; k += blockDim.x) {
        float v = tsh[k];
        float dl = (k < TABN - 1) ? (tsh[k + 1] - v) : 0.f;
        g_tab[f * TABN + k] = make_float2(v, dl);
    }
}

// ---------------- K2: fused conv -> RBF -> conv^T -> residual (HFMA2, reg weights) ----------------
__global__ void __launch_bounds__(256, 2)
main_kernel(const float* __restrict__ input, const float* __restrict__ net_input) {
    __shared__ __align__(16) half xs[76 * XS];
    __shared__ __align__(16) half as_h[70 * AS];
    __shared__ float red[8];

    int blk  = blockIdx.x;
    int b    = blk >> 4;
    int tile = blk & 15;
    int ty0  = (tile >> 2) << 6;
    int tx0  = (tile & 3) << 6;
    int tid  = threadIdx.x;

    const float* ibase = input + b * IMG * IMG;

    // load x halo (76 rows x 78 cols used) with symmetric reflection -> fp16
    for (int idx = tid; idx < 76 * XS; idx += 256) {
        int ri = idx / XS, ci = idx - ri * XS;
        float v = 0.f;
        if (ci < 78) {
            int gy = ty0 + ri - 6, gx = tx0 + ci - 6;
            gy = (gy < 0) ? (-1 - gy) : ((gy >= IMG) ? (2 * IMG - 1 - gy) : gy);
            gx = (gx < 0) ? (-1 - gx) : ((gx >= IMG) ? (2 * IMG - 1 - gx) : gx);
            v = ibase[gy * IMG + gx];
        }
        xs[ri * XS + ci] = __float2half(v);
    }

    bool actA = tid < 252;
    int rg = tid / 18, cg = tid - rg * 18;
    int r0 = -3 + 5 * rg;
    int c0 = -3 + 4 * cg;

    int tyq = tid >> 4, txq = tid & 15;
    int ob = tyq << 2, oc = txq << 2;

    float oacc[16];
    #pragma unroll
    for (int i = 0; i < 16; i++) oacc[i] = 0.f;

    __syncthreads();

    #pragma unroll 1
    for (int f = 0; f < NF; f++) {
        // ---- phase A: forward conv (half2), z kept in za across the barrier ----
        half2 za[10];
        if (actA) {
            uint32_t wb[52];
            const uint4* wp = (const uint4*)(g_wb + f * 52);
            #pragma unroll
            for (int v = 0; v < 13; v++) {
                uint4 t = __ldg(wp + v);
                wb[4 * v] = t.x; wb[4 * v + 1] = t.y; wb[4 * v + 2] = t.z; wb[4 * v + 3] = t.w;
            }
            #pragma unroll
            for (int i = 0; i < 10; i++) za[i] = __float2half2_rn(0.f);

            #pragma unroll
            for (int wr = 0; wr < 11; wr++) {
                const half* xp = xs + (r0 + 3 + wr) * XS + 4 * cg;
                half2 P[5], O[4];
                #pragma unroll
                for (int k = 0; k < 5; k++) P[k] = *(const half2*)(xp + 2 * k);
                #pragma unroll
                for (int k = 0; k < 4; k++)
                    O[k] = __halves2half2(__high2half(P[k]), __low2half(P[k + 1]));
                #pragma unroll
                for (int i = 0; i < 5; i++) {
                    int p = wr - i;
                    if (p >= 0 && p < 7) {
                        const uint32_t* w = wb + p * 7;
                        half2 a0 = za[i * 2], a1 = za[i * 2 + 1];
                        a0 = __hfma2(u2h(w[0]), P[0], a0);  a1 = __hfma2(u2h(w[0]), P[1], a1);
                        a0 = __hfma2(u2h(w[1]), O[0], a0);  a1 = __hfma2(u2h(w[1]), O[1], a1);
                        a0 = __hfma2(u2h(w[2]), P[1], a0);  a1 = __hfma2(u2h(w[2]), P[2], a1);
                        a0 = __hfma2(u2h(w[3]), O[1], a0);  a1 = __hfma2(u2h(w[3]), O[2], a1);
                        a0 = __hfma2(u2h(w[4]), P[2], a0);  a1 = __hfma2(u2h(w[4]), P[3], a1);
                        a0 = __hfma2(u2h(w[5]), O[2], a0);  a1 = __hfma2(u2h(w[5]), O[3], a1);
                        a0 = __hfma2(u2h(w[6]), P[3], a0);  a1 = __hfma2(u2h(w[6]), P[4], a1);
                        za[i * 2] = a0; za[i * 2 + 1] = a1;
                    }
                }
            }
        }
        __syncthreads();   // previous phase-B readers of as_h done
        if (actA) {
            // RBF lerp fused with the a-store (no aout array)
            const float2* tb = g_tab + f * TABN;
            #pragma unroll
            for (int i = 0; i < 5; i++) {
                int gr = ty0 + r0 + i;
                bool rok = (gr >= 0) && (gr < IMG);
                float2 zl = __half22float2(za[i * 2]);
                float2 zh = __half22float2(za[i * 2 + 1]);
                float zv[4] = {zl.x, zl.y, zh.x, zh.y};
                float av[4];
                #pragma unroll
                for (int j = 0; j < 4; j++) {
                    float t = (zv[j] + 16.f) * 64.f;
                    t = fminf(fmaxf(t, 0.f), 2047.99f);
                    int ix = (int)t;
                    float fr = t - (float)ix;
                    float2 tv = __ldg(tb + ix);
                    float a = tv.x + fr * tv.y;
                    int gc = tx0 + c0 + j;
                    if (!rok || gc < 0 || gc >= IMG) a = 0.f;
                    av[j] = a;
                }
                half* dst = as_h + (r0 + i + 3) * AS + 4 * cg;
                *(half2*)dst       = __floats2half2_rn(av[0], av[1]);
                *(half2*)(dst + 2) = __floats2half2_rn(av[2], av[3]);
            }
        }
        __syncthreads();   // a tile ready

        // ---- phase B: conv^T (reversed weights in regs, half2, fp32 fold) ----
        {
            uint32_t wb[52];
            const uint4* wp = (const uint4*)(g_wbr + f * 52);
            #pragma unroll
            for (int v = 0; v < 13; v++) {
                uint4 t = __ldg(wp + v);
                wb[4 * v] = t.x; wb[4 * v + 1] = t.y; wb[4 * v + 2] = t.z; wb[4 * v + 3] = t.w;
            }
            half2 ga[8];
            #pragma unroll
            for (int i = 0; i < 8; i++) ga[i] = __float2half2_rn(0.f);

            #pragma unroll
            for (int wrb = 0; wrb < 10; wrb++) {
                const half* ap = as_h + (ob + wrb) * AS + oc;
                half2 P[5], O[4];
                #pragma unroll
                for (int k = 0; k < 5; k++) P[k] = *(const half2*)(ap + 2 * k);
                #pragma unroll
                for (int k = 0; k < 4; k++)
                    O[k] = __halves2half2(__high2half(P[k]), __low2half(P[k + 1]));
                #pragma unroll
                for (int i = 0; i < 4; i++) {
                    int p = wrb - i;
                    if (p >= 0 && p < 7) {
                        const uint32_t* w = wb + p * 7;
                        half2 a0 = ga[i * 2], a1 = ga[i * 2 + 1];
                        a0 = __hfma2(u2h(w[0]), P[0], a0);  a1 = __hfma2(u2h(w[0]), P[1], a1);
                        a0 = __hfma2(u2h(w[1]), O[0], a0);  a1 = __hfma2(u2h(w[1]), O[1], a1);
                        a0 = __hfma2(u2h(w[2]), P[1], a0);  a1 = __hfma2(u2h(w[2]), P[2], a1);
                        a0 = __hfma2(u2h(w[3]), O[1], a0);  a1 = __hfma2(u2h(w[3]), O[2], a1);
                        a0 = __hfma2(u2h(w[4]), P[2], a0);  a1 = __hfma2(u2h(w[4]), P[3], a1);
                        a0 = __hfma2(u2h(w[5]), O[2], a0);  a1 = __hfma2(u2h(w[5]), O[3], a1);
                        a0 = __hfma2(u2h(w[6]), P[3], a0);  a1 = __hfma2(u2h(w[6]), P[4], a1);
                        ga[i * 2] = a0; ga[i * 2 + 1] = a1;
                    }
                }
            }
            #pragma unroll
            for (int i = 0; i < 4; i++) {
                float2 lo = __half22float2(ga[i * 2]);
                float2 hi = __half22float2(ga[i * 2 + 1]);
                oacc[i * 4 + 0] += lo.x; oacc[i * 4 + 1] += lo.y;
                oacc[i * 4 + 2] += hi.x; oacc[i * 4 + 3] += hi.y;
            }
        }
    }

    // epilogue: r = input - convt - net_input ; per-block sum(r^2)
    const float* nbase = net_input + b * IMG * IMG;
    float* rbase = g_r + b * IMG * IMG;
    float ss = 0.f;
    #pragma unroll
    for (int i = 0; i < 4; i++) {
        int gy = ty0 + ob + i;
        int go = gy * IMG + tx0 + oc;
        float4 iv = *(const float4*)(ibase + go);
        float4 nv = *(const float4*)(nbase + go);
        float4 rv;
        rv.x = iv.x - oacc[i * 4 + 0] - nv.x;
        rv.y = iv.y - oacc[i * 4 + 1] - nv.y;
        rv.z = iv.z - oacc[i * 4 + 2] - nv.z;
        rv.w = iv.w - oacc[i * 4 + 3] - nv.w;
        *(float4*)(rbase + go) = rv;
        ss += rv.x * rv.x + rv.y * rv.y + rv.z * rv.z + rv.w * rv.w;
    }
    #pragma unroll
    for (int o = 16; o > 0; o >>= 1) ss += __shfl_down_sync(0xffffffffu, ss, o);
    if ((tid & 31) == 0) red[tid >> 5] = ss;
    __syncthreads();
    if (tid == 0) {
        float s = 0.f;
        #pragma unroll
        for (int w = 0; w < 8; w++) s += red[w];
        g_partial[blk] = s;
    }
}

// ---------------- K3: scale (folded) + out = net_input + r*scale ----------------
__global__ void final_kernel(const float* __restrict__ net_input,
                             const float* __restrict__ stdn,
                             const float* __restrict__ alpha,
                             float* __restrict__ out) {
    __shared__ float sc_sh;
    int v = blockIdx.x * blockDim.x + threadIdx.x;
    int b = v >> 14;   // 16384 float4 per batch
    if (threadIdx.x == 0) {
        float s = 0.f;
        #pragma unroll
        for (int t = 0; t < 16; t++) s += g_partial[b * 16 + t];
        float nr = sqrtf(s);
        float k = expf(alpha[0]) * stdn[b] * 256.f;
        sc_sh = fminf(1.f, k / (nr + 1e-12f));
    }
    __syncthreads();
    float sc = sc_sh;
    float4 rr = ((const float4*)g_r)[v];
    float4 nn = ((const float4*)net_input)[v];
    float4 o;
    o.x = nn.x + rr.x * sc;
    o.y = nn.y + rr.y * sc;
    o.z = nn.z + rr.z * sc;
    o.w = nn.w + rr.w * sc;
    ((float4*)out)[v] = o;
}

extern "C" void kernel_launch(void* const* d_in, const int* in_sizes, int n_in,
                              void* d_out, int out_size) {
    const float* input     = (const float*)d_in[0];
    const float* stdn      = (const float*)d_in[1];
    const float* net_input = (const float*)d_in[3];
    const float* cw        = (const float*)d_in[4];
    const float* sf        = (const float*)d_in[5];
    const float* alpha     = (const float*)d_in[6];
    const float* rbw       = (const float*)d_in[7];
    const float* rbc       = (const float*)d_in[8];
    float* out = (float*)d_out;

    prep_table_kernel<<<NF, 256>>>(cw, sf, rbw, rbc);
    main_kernel<<<256, 256>>>(input, net_input);
    final_kernel<<<1024, 256>>>(net_input, stdn, alpha, out);
}

// round 8
// speedup vs baseline: 2.7745x; 1.4444x over previous
#include <cuda_runtime.h>
#include <cuda_bf16.h>
#include <math.h>
#include <stdint.h>

#define NF   48
#define NM   51
#define IMG  256
#define TABN 2049

// ---- dynamic smem layout (bytes) ----
#define XCPY   10944            // one shifted x copy: 76 rows * 72 halves * 2B
#define A1_OFF 21888            // 4 warp regions * 32 rows * 144B
#define B1_OFF 40320            // 48 rows * 144B
#define B2_OFF 47232            // 56 rows * 144B
#define G_OFF  55296            // ring: 10 * GROWR
#define GROWR  7424             // 64 px * 116B
#define RED_OFF 129536
#define SMEM_TOTAL 129600

// ---- device scratch ----
__device__ __align__(16) __nv_bfloat16 g_B1[NF * 64];   // [f][k=p*8+q]
__device__ __align__(16) __nv_bfloat16 g_B2[64 * 64];   // [n=p*8+q][f] (f>=48 zero)
__device__ float2 g_tab[NF * TABN];
__device__ float  g_r[16 * IMG * IMG];
__device__ float  g_partial[16 * 20];

__device__ __forceinline__ void mma_bf16(float c[4], const uint32_t a[4],
                                         uint32_t b0, uint32_t b1) {
    asm volatile("mma.sync.aligned.m16n8k16.row.col.f32.bf16.bf16.f32 "
        "{%0,%1,%2,%3}, {%4,%5,%6,%7}, {%8,%9}, {%0,%1,%2,%3};"
        : "+f"(c[0]), "+f"(c[1]), "+f"(c[2]), "+f"(c[3])
        : "r"(a[0]), "r"(a[1]), "r"(a[2]), "r"(a[3]), "r"(b0), "r"(b1));
}
__device__ __forceinline__ uint32_t bfpk(float hi, float lo) {
    uint32_t r; asm("cvt.rn.bf16x2.f32 %0, %1, %2;" : "=r"(r) : "f"(hi), "f"(lo)); return r;
}

// ---------------- K1: normalize weights -> B1/B2 bf16 + RBF tables ----------------
__global__ void prep_kernel(const float* __restrict__ cw, const float* __restrict__ sf,
                            const float* __restrict__ rbw, const float* __restrict__ rbc) {
    __shared__ float wn[49];
    __shared__ float msh[2];
    __shared__ float wsh[NM], csh[NM];
    __shared__ float tsh[TABN];
    int f = blockIdx.x, tid = threadIdx.x;

    if (tid < 49) wn[tid] = cw[f * 49 + tid];
    if (tid < NM) { wsh[tid] = rbw[f * NM + tid]; csh[tid] = rbc[tid]; }
    __syncthreads();
    if (tid == 0) {
        float mean = 0.f;
        #pragma unroll
        for (int i = 0; i < 49; i++) mean += wn[i];
        mean *= (1.f / 49.f);
        float ssq = 0.f;
        #pragma unroll
        for (int i = 0; i < 49; i++) { float d = wn[i] - mean; ssq += d * d; }
        msh[0] = mean;
        msh[1] = sf[f] / (sqrtf(ssq) + 1e-12f);
    }
    __syncthreads();
    if (tid < 49) wn[tid] = (wn[tid] - msh[0]) * msh[1];
    __syncthreads();
    if (tid < 64) {
        int p = tid >> 3, q = tid & 7;
        float v = (p < 7 && q < 7) ? wn[p * 7 + q] : 0.f;
        g_B1[f * 64 + tid] = __float2bfloat16(v);   // [f][k]
        g_B2[tid * 64 + f] = __float2bfloat16(v);   // [n][f]
    }
    for (int k = tid; k < TABN; k += blockDim.x) {
        float z = -16.f + (float)k * (1.f / 64.f);
        float acc = 0.f;
        #pragma unroll
        for (int m = 0; m < NM; m++) {
            float d = z - csh[m];
            acc += wsh[m] * __expf(-0.01f * d * d);
        }
        tsh[k] = acc;
    }
    __syncthreads();
    for (int k = tid; k < TABN; k += blockDim.x) {
        float v = tsh[k];
        float dl = (k < TABN - 1) ? (tsh[k + 1] - v) : 0.f;
        g_tab[f * TABN + k] = make_float2(v, dl);
    }
}

// ---------------- K2: fused tensor-core main (mma.sync) ----------------
// grid 320 = 16 img x 4 ytiles x 5 xtiles; 256 threads
__global__ void __launch_bounds__(256)
main_kernel(const float* __restrict__ input, const float* __restrict__ net_input) {
    extern __shared__ __align__(16) char smem[];

    int bid = blockIdx.x;
    int img = bid / 20;
    int rr  = bid % 20;
    int y0 = (rr / 5) * 64;
    int x0 = (rr % 5) * 58;
    int tid  = threadIdx.x;
    int wid  = tid >> 5;
    int lane = tid & 31;

    const float* ibase = input + img * IMG * IMG;
    const float* nbase = net_input + img * IMG * IMG;

    // ---- stage x halo: 2 shifted bf16 copies (76 rows x 71 cols) ----
    __nv_bfloat16* xs0 = (__nv_bfloat16*)smem;
    __nv_bfloat16* xs1 = (__nv_bfloat16*)(smem + XCPY);
    for (int idx = tid; idx < 76 * 71; idx += 256) {
        int xr = idx / 71, xc = idx - xr * 71;
        int gy = y0 - 6 + xr, gx = x0 - 6 + xc;
        gy = (gy < 0) ? (-1 - gy) : ((gy >= IMG) ? (2 * IMG - 1 - gy) : gy);
        gx = (gx < 0) ? (-1 - gx) : ((gx >= IMG) ? (2 * IMG - 1 - gx) : gx);
        __nv_bfloat16 v = __float2bfloat16(ibase[gy * IMG + gx]);
        xs0[xr * 72 + xc] = v;
        if (xc >= 1) xs1[xr * 72 + xc - 1] = v;
    }
    // ---- stage B1 (48x64, stride 72h) and B2 (56x64, stride 72h) ----
    for (int i = tid; i < 48 * 8; i += 256) {
        int r = i >> 3, cj = i & 7;
        *(uint4*)(smem + B1_OFF + r * 144 + cj * 16) = *(const uint4*)(g_B1 + r * 64 + cj * 8);
    }
    for (int i = tid; i < 56 * 8; i += 256) {
        int r = i >> 3, cj = i & 7;
        *(uint4*)(smem + B2_OFF + r * 144 + cj * 16) = *(const uint4*)(g_B2 + r * 64 + cj * 8);
    }
    // ---- zero A1 chunk 7 (k=56..63 stays zero forever) ----
    if (tid < 128) {
        uint4 z; z.x = 0; z.y = 0; z.z = 0; z.w = 0;
        *(uint4*)(smem + A1_OFF + tid * 144 + 112) = z;
    }
    __syncthreads();

    int g  = lane >> 2;       // 0..7
    int tg = lane & 3;        // 0..3
    float ss = 0.f;

    // produce-warp constants
    int ca0    = (wid & 1) * 32;
    int rahalf = wid >> 1;
    char* Awarp = smem + A1_OFF + wid * 32 * 144;
    int caL  = ca0 + lane;               // im2col pixel col for this lane
    int cpySel = (caL & 1);
    int colB = caL - cpySel;             // 4B-aligned half index
    const char* xcopy = smem + cpySel * XCPY;

    // gather-warp constants
    int j  = tid - 128;
    int xl = j & 63;
    int yh = j >> 6;

    #pragma unroll 1
    for (int s = 0; s < 36; s++) {
        __syncthreads();
        if (wid < 4) {
            if (s < 35) {
                int ra = 2 * s + rahalf;
                // ---- im2col: lane builds its pixel's 7 chunks ----
                #pragma unroll
                for (int p = 0; p < 7; p++) {
                    const char* src = xcopy + ((ra + p) * 72 + colB) * 2;
                    uint32_t w0 = *(const uint32_t*)src;
                    uint32_t w1 = *(const uint32_t*)(src + 4);
                    uint32_t w2 = *(const uint32_t*)(src + 8);
                    uint32_t w3 = *(const uint32_t*)(src + 12);
                    uint4 st; st.x = w0; st.y = w1; st.z = w2; st.w = w3;
                    *(uint4*)(Awarp + lane * 144 + p * 16) = st;
                }
                __syncwarp();

                // ---- GEMM1: D1[32pix x 48f] = A1[32x64] * B1[64x48] ----
                float d1[2][6][4];
                #pragma unroll
                for (int m = 0; m < 2; m++)
                    #pragma unroll
                    for (int n = 0; n < 6; n++)
                        #pragma unroll
                        for (int e = 0; e < 4; e++) d1[m][n][e] = 0.f;
                #pragma unroll
                for (int k = 0; k < 4; k++) {
                    uint32_t afr[2][4];
                    #pragma unroll
                    for (int m = 0; m < 2; m++) {
                        const char* ab = Awarp + (m * 16 + g) * 144 + (k * 16 + tg * 2) * 2;
                        afr[m][0] = *(const uint32_t*)ab;
                        afr[m][1] = *(const uint32_t*)(ab + 8 * 144);
                        afr[m][2] = *(const uint32_t*)(ab + 16);
                        afr[m][3] = *(const uint32_t*)(ab + 8 * 144 + 16);
                    }
                    #pragma unroll
                    for (int n = 0; n < 6; n++) {
                        const char* bb = smem + B1_OFF + (n * 8 + g) * 144 + (k * 16 + tg * 2) * 2;
                        uint32_t b0 = *(const uint32_t*)bb;
                        uint32_t b1 = *(const uint32_t*)(bb + 16);
                        mma_bf16(d1[0][n], afr[0], b0, b1);
                        mma_bf16(d1[1][n], afr[1], b0, b1);
                    }
                }

                // ---- RBF lerp in-register (+ zero outside image) ----
                int u = y0 - 3 + ra;
                bool uok = (u >= 0) && (u < IMG);
                #pragma unroll
                for (int m = 0; m < 2; m++) {
                    int vA = x0 - 3 + ca0 + m * 16 + g;
                    int vB = vA + 8;
                    bool okA = uok && (vA >= 0) && (vA < IMG);
                    bool okB = uok && (vB >= 0) && (vB < IMG);
                    #pragma unroll
                    for (int n = 0; n < 6; n++) {
                        #pragma unroll
                        for (int e = 0; e < 4; e++) {
                            bool ok = (e < 2) ? okA : okB;
                            int fidx = n * 8 + tg * 2 + (e & 1);
                            float z = d1[m][n][e];
                            float t = fminf(fmaxf((z + 16.f) * 64.f, 0.f), 2047.99f);
                            int ix = (int)t;
                            float fr = t - (float)ix;
                            float2 tv = __ldg(&g_tab[fidx * TABN + ix]);
                            float a = tv.x + fr * tv.y;
                            d1[m][n][e] = ok ? a : 0.f;
                        }
                    }
                }

                // ---- repack D1 -> A fragments of GEMM2 (register-only) ----
                uint32_t a2[2][3][4];
                #pragma unroll
                for (int m = 0; m < 2; m++)
                    #pragma unroll
                    for (int t = 0; t < 3; t++) {
                        a2[m][t][0] = bfpk(d1[m][2 * t][1],     d1[m][2 * t][0]);
                        a2[m][t][1] = bfpk(d1[m][2 * t][3],     d1[m][2 * t][2]);
                        a2[m][t][2] = bfpk(d1[m][2 * t + 1][1], d1[m][2 * t + 1][0]);
                        a2[m][t][3] = bfpk(d1[m][2 * t + 1][3], d1[m][2 * t + 1][2]);
                    }

                // ---- GEMM2: G[32pix x 56n] = A2[32x48] * B2[48x56] ----
                float d2[2][7][4];
                #pragma unroll
                for (int m = 0; m < 2; m++)
                    #pragma unroll
                    for (int n = 0; n < 7; n++)
                        #pragma unroll
                        for (int e = 0; e < 4; e++) d2[m][n][e] = 0.f;
                #pragma unroll
                for (int k = 0; k < 3; k++) {
                    #pragma unroll
                    for (int n = 0; n < 7; n++) {
                        const char* bb = smem + B2_OFF + (n * 8 + g) * 144 + (k * 16 + tg * 2) * 2;
                        uint32_t b0 = *(const uint32_t*)bb;
                        uint32_t b1 = *(const uint32_t*)(bb + 16);
                        mma_bf16(d2[0][n], a2[0][k], b0, b1);
                        mma_bf16(d2[1][n], a2[1][k], b0, b1);
                    }
                }

                // ---- store G ring (bf16, px stride 116B) ----
                char* grow = smem + G_OFF + (ra % 10) * GROWR;
                #pragma unroll
                for (int m = 0; m < 2; m++) {
                    int pxA = ca0 + m * 16 + g;
                    #pragma unroll
                    for (int n = 0; n < 7; n++) {
                        uint32_t lo = bfpk(d2[m][n][1], d2[m][n][0]);
                        uint32_t hi = bfpk(d2[m][n][3], d2[m][n][2]);
                        int noff = (n * 8 + tg * 2) * 2;
                        *(uint32_t*)(grow + pxA * 116 + noff) = lo;
                        *(uint32_t*)(grow + (pxA + 8) * 116 + noff) = hi;
                    }
                }
            }
        } else {
            // ---- gather warps: col2im + residual for y rows 2(s-4), 2(s-4)+1 ----
            if (s >= 4) {
                int yl = 2 * (s - 4) + yh;
                int xg = x0 + xl;
                if (xl < 58 && xg < IMG) {
                    float cv = 0.f;
                    #pragma unroll
                    for (int p = 0; p < 7; p++) {
                        const char* rb = smem + G_OFF + ((yl + 6 - p) % 10) * GROWR + p * 16;
                        #pragma unroll
                        for (int q = 0; q < 7; q++) {
                            uint16_t gv = *(const uint16_t*)(rb + (xl + 6 - q) * 116 + q * 2);
                            cv += __uint_as_float((uint32_t)gv << 16);
                        }
                    }
                    int yg = y0 + yl;
                    float iv = ibase[yg * IMG + xg];
                    float nv = nbase[yg * IMG + xg];
                    float rv = iv - cv - nv;
                    g_r[img * IMG * IMG + yg * IMG + xg] = rv;
                    ss += rv * rv;
                }
            }
        }
    }

    __syncthreads();
    float* red = (float*)(smem + RED_OFF);
    #pragma unroll
    for (int o = 16; o > 0; o >>= 1) ss += __shfl_down_sync(0xffffffffu, ss, o);
    if (lane == 0) red[wid] = ss;
    __syncthreads();
    if (tid == 0) {
        float t = 0.f;
        #pragma unroll
        for (int w = 0; w < 8; w++) t += red[w];
        g_partial[img * 20 + rr] = t;
    }
}

// ---------------- K3: scale + out = net_input + r*scale ----------------
__global__ void final_kernel(const float* __restrict__ net_input,
                             const float* __restrict__ stdn,
                             const float* __restrict__ alpha,
                             float* __restrict__ out) {
    __shared__ float sc_sh;
    int v = blockIdx.x * blockDim.x + threadIdx.x;  // float4 index
    int b = v >> 14;
    if (threadIdx.x == 0) {
        float s = 0.f;
        #pragma unroll
        for (int t = 0; t < 20; t++) s += g_partial[b * 20 + t];
        float nr = sqrtf(s);
        float k = expf(alpha[0]) * stdn[b] * 256.f;
        sc_sh = fminf(1.f, k / (nr + 1e-12f));
    }
    __syncthreads();
    float sc = sc_sh;
    float4 rr = ((const float4*)g_r)[v];
    float4 nn = ((const float4*)net_input)[v];
    float4 o;
    o.x = nn.x + rr.x * sc;
    o.y = nn.y + rr.y * sc;
    o.z = nn.z + rr.z * sc;
    o.w = nn.w + rr.w * sc;
    ((float4*)out)[v] = o;
}

extern "C" void kernel_launch(void* const* d_in, const int* in_sizes, int n_in,
                              void* d_out, int out_size) {
    const float* input     = (const float*)d_in[0];
    const float* stdn      = (const float*)d_in[1];
    const float* net_input = (const float*)d_in[3];
    const float* cw        = (const float*)d_in[4];
    const float* sf        = (const float*)d_in[5];
    const float* alpha     = (const float*)d_in[6];
    const float* rbw       = (const float*)d_in[7];
    const float* rbc       = (const float*)d_in[8];
    float* out = (float*)d_out;

    cudaFuncSetAttribute(main_kernel, cudaFuncAttributeMaxDynamicSharedMemorySize, SMEM_TOTAL);

    prep_kernel<<<NF, 256>>>(cw, sf, rbw, rbc);
    main_kernel<<<320, 256, SMEM_TOTAL>>>(input, net_input);
    final_kernel<<<1024, 256>>>(net_input, stdn, alpha, out);
}

// round 9
// speedup vs baseline: 3.0588x; 1.1025x over previous
#include <cuda_runtime.h>
#include <cuda_bf16.h>
#include <math.h>
#include <stdint.h>

#define NF   48
#define NM   51
#define IMG  256
#define TABN 2049

// ---- dynamic smem layout (bytes) ----
#define XCPY   10944            // one shifted x copy: 76 rows * 72 halves * 2B
#define A1_OFF 21888            // 8 warp regions * 32 rows * 144B = 36864
#define B1_OFF 58752            // 48 rows * 144B = 6912
#define B2_OFF 65664            // 56 rows * 144B = 8064
#define G_OFF  73728            // ring: 16 * GROWR = 118784
#define GROWR  7424             // 64 px * 116B
#define RED_OFF 192512
#define SMEM_TOTAL 192576

// ---- device scratch ----
__device__ __align__(16) __nv_bfloat16 g_B1[NF * 64];   // [f][k=p*8+q]
__device__ __align__(16) __nv_bfloat16 g_B2[64 * 64];   // [n=p*8+q][f] (f>=48 zero)
__device__ float2 g_tab[NF * TABN];
__device__ float  g_r[16 * IMG * IMG];
__device__ float  g_partial[16 * 20];

__device__ __forceinline__ void mma_bf16(float c[4], const uint32_t a[4],
                                         uint32_t b0, uint32_t b1) {
    asm volatile("mma.sync.aligned.m16n8k16.row.col.f32.bf16.bf16.f32 "
        "{%0,%1,%2,%3}, {%4,%5,%6,%7}, {%8,%9}, {%0,%1,%2,%3};"
        : "+f"(c[0]), "+f"(c[1]), "+f"(c[2]), "+f"(c[3])
        : "r"(a[0]), "r"(a[1]), "r"(a[2]), "r"(a[3]), "r"(b0), "r"(b1));
}
__device__ __forceinline__ uint32_t bfpk(float hi, float lo) {
    uint32_t r; asm("cvt.rn.bf16x2.f32 %0, %1, %2;" : "=r"(r) : "f"(hi), "f"(lo)); return r;
}

// ---------------- K1: normalize weights -> B1/B2 bf16 + RBF tables ----------------
__global__ void prep_kernel(const float* __restrict__ cw, const float* __restrict__ sf,
                            const float* __restrict__ rbw, const float* __restrict__ rbc) {
    __shared__ float wn[49];
    __shared__ float msh[2];
    __shared__ float wsh[NM], csh[NM];
    __shared__ float tsh[TABN];
    int f = blockIdx.x, tid = threadIdx.x;

    if (tid < 49) wn[tid] = cw[f * 49 + tid];
    if (tid < NM) { wsh[tid] = rbw[f * NM + tid]; csh[tid] = rbc[tid]; }
    __syncthreads();
    if (tid == 0) {
        float mean = 0.f;
        #pragma unroll
        for (int i = 0; i < 49; i++) mean += wn[i];
        mean *= (1.f / 49.f);
        float ssq = 0.f;
        #pragma unroll
        for (int i = 0; i < 49; i++) { float d = wn[i] - mean; ssq += d * d; }
        msh[0] = mean;
        msh[1] = sf[f] / (sqrtf(ssq) + 1e-12f);
    }
    __syncthreads();
    if (tid < 49) wn[tid] = (wn[tid] - msh[0]) * msh[1];
    __syncthreads();
    if (tid < 64) {
        int p = tid >> 3, q = tid & 7;
        float v = (p < 7 && q < 7) ? wn[p * 7 + q] : 0.f;
        g_B1[f * 64 + tid] = __float2bfloat16(v);   // [f][k]
        g_B2[tid * 64 + f] = __float2bfloat16(v);   // [n][f]
    }
    for (int k = tid; k < TABN; k += blockDim.x) {
        float z = -16.f + (float)k * (1.f / 64.f);
        float acc = 0.f;
        #pragma unroll
        for (int m = 0; m < NM; m++) {
            float d = z - csh[m];
            acc += wsh[m] * __expf(-0.01f * d * d);
        }
        tsh[k] = acc;
    }
    __syncthreads();
    for (int k = tid; k < TABN; k += blockDim.x) {
        float v = tsh[k];
        float dl = (k < TABN - 1) ? (tsh[k + 1] - v) : 0.f;
        g_tab[f * TABN + k] = make_float2(v, dl);
    }
}

// ---------------- K2: fused tensor-core main (mma.sync, 8 worker warps) ----------------
// grid 320 = 16 img x 4 ytiles x 5 xtiles; 256 threads
__global__ void __launch_bounds__(256)
main_kernel(const float* __restrict__ input, const float* __restrict__ net_input) {
    extern __shared__ __align__(16) char smem[];

    int bid = blockIdx.x;
    int img = bid / 20;
    int rr  = bid % 20;
    int y0 = (rr / 5) * 64;
    int x0 = (rr % 5) * 58;
    int tid  = threadIdx.x;
    int wid  = tid >> 5;
    int lane = tid & 31;

    const float* ibase = input + img * IMG * IMG;
    const float* nbase = net_input + img * IMG * IMG;

    // ---- stage x halo: 2 shifted bf16 copies (76 rows x 71 cols) ----
    __nv_bfloat16* xs0 = (__nv_bfloat16*)smem;
    __nv_bfloat16* xs1 = (__nv_bfloat16*)(smem + XCPY);
    for (int idx = tid; idx < 76 * 71; idx += 256) {
        int xr = idx / 71, xc = idx - xr * 71;
        int gy = y0 - 6 + xr, gx = x0 - 6 + xc;
        gy = (gy < 0) ? (-1 - gy) : ((gy >= IMG) ? (2 * IMG - 1 - gy) : gy);
        gx = (gx < 0) ? (-1 - gx) : ((gx >= IMG) ? (2 * IMG - 1 - gx) : gx);
        __nv_bfloat16 v = __float2bfloat16(ibase[gy * IMG + gx]);
        xs0[xr * 72 + xc] = v;
        if (xc >= 1) xs1[xr * 72 + xc - 1] = v;
    }
    // ---- stage B1 (48x64) and B2 (56x64), row stride 144B ----
    for (int i = tid; i < 48 * 8; i += 256) {
        int r = i >> 3, cj = i & 7;
        *(uint4*)(smem + B1_OFF + r * 144 + cj * 16) = *(const uint4*)(g_B1 + r * 64 + cj * 8);
    }
    for (int i = tid; i < 56 * 8; i += 256) {
        int r = i >> 3, cj = i & 7;
        *(uint4*)(smem + B2_OFF + r * 144 + cj * 16) = *(const uint4*)(g_B2 + r * 64 + cj * 8);
    }
    // ---- zero A1 chunk 7 for all 256 rows (k=56..63 stays zero forever) ----
    {
        uint4 z; z.x = 0; z.y = 0; z.z = 0; z.w = 0;
        *(uint4*)(smem + A1_OFF + tid * 144 + 112) = z;
    }
    __syncthreads();

    int g  = lane >> 2;       // 0..7
    int tg = lane & 3;        // 0..3
    float ss = 0.f;

    // worker constants: warp handles a-row 4s + (wid>>2... wid>>1), cols (wid&1)*32 ..+31
    int ca0    = (wid & 1) * 32;
    int rquart = wid >> 1;               // 0..3
    char* Awarp = smem + A1_OFF + wid * 32 * 144;
    int caL  = ca0 + lane;               // im2col pixel col for this lane
    int cpySel = (caL & 1);
    int colB = caL - cpySel;             // 4B-aligned half index
    const char* xcopy = smem + cpySel * XCPY;

    // gather constants
    int xl = tid & 63;
    int yh = tid >> 6;                   // 0..3

    #pragma unroll 1
    for (int s = 0; s < 19; s++) {
        __syncthreads();   // orders prev slab G-stores before this slab's gathers,
                           // and prev gathers before ring-slot reuse

        int ra = 4 * s + rquart;
        if (ra < 70) {
            // ---- im2col: lane builds its pixel's 7 chunks ----
            #pragma unroll
            for (int p = 0; p < 7; p++) {
                const char* src = xcopy + ((ra + p) * 72 + colB) * 2;
                uint32_t w0 = *(const uint32_t*)src;
                uint32_t w1 = *(const uint32_t*)(src + 4);
                uint32_t w2 = *(const uint32_t*)(src + 8);
                uint32_t w3 = *(const uint32_t*)(src + 12);
                uint4 st; st.x = w0; st.y = w1; st.z = w2; st.w = w3;
                *(uint4*)(Awarp + lane * 144 + p * 16) = st;
            }
            __syncwarp();

            // ---- GEMM1: D1[32px x 48f] = A1[32x64] * B1[64x48] ----
            float d1[2][6][4];
            #pragma unroll
            for (int m = 0; m < 2; m++)
                #pragma unroll
                for (int n = 0; n < 6; n++)
                    #pragma unroll
                    for (int e = 0; e < 4; e++) d1[m][n][e] = 0.f;
            #pragma unroll
            for (int k = 0; k < 4; k++) {
                uint32_t afr[2][4];
                #pragma unroll
                for (int m = 0; m < 2; m++) {
                    const char* ab = Awarp + (m * 16 + g) * 144 + (k * 16 + tg * 2) * 2;
                    afr[m][0] = *(const uint32_t*)ab;
                    afr[m][1] = *(const uint32_t*)(ab + 8 * 144);
                    afr[m][2] = *(const uint32_t*)(ab + 16);
                    afr[m][3] = *(const uint32_t*)(ab + 8 * 144 + 16);
                }
                #pragma unroll
                for (int n = 0; n < 6; n++) {
                    const char* bb = smem + B1_OFF + (n * 8 + g) * 144 + (k * 16 + tg * 2) * 2;
                    uint32_t b0 = *(const uint32_t*)bb;
                    uint32_t b1 = *(const uint32_t*)(bb + 16);
                    mma_bf16(d1[0][n], afr[0], b0, b1);
                    mma_bf16(d1[1][n], afr[1], b0, b1);
                }
            }

            // ---- RBF lerp in-register (+ zero outside image) ----
            int u = y0 - 3 + ra;
            bool uok = (u >= 0) && (u < IMG);
            #pragma unroll
            for (int m = 0; m < 2; m++) {
                int vA = x0 - 3 + ca0 + m * 16 + g;
                int vB = vA + 8;
                bool okA = uok && (vA >= 0) && (vA < IMG);
                bool okB = uok && (vB >= 0) && (vB < IMG);
                #pragma unroll
                for (int n = 0; n < 6; n++) {
                    #pragma unroll
                    for (int e = 0; e < 4; e++) {
                        bool ok = (e < 2) ? okA : okB;
                        int fidx = n * 8 + tg * 2 + (e & 1);
                        float z = d1[m][n][e];
                        float t = fminf(fmaxf((z + 16.f) * 64.f, 0.f), 2047.99f);
                        int ix = (int)t;
                        float fr = t - (float)ix;
                        float2 tv = __ldg(&g_tab[fidx * TABN + ix]);
                        float a = tv.x + fr * tv.y;
                        d1[m][n][e] = ok ? a : 0.f;
                    }
                }
            }

            // ---- repack D1 -> A fragments of GEMM2 (register-only) ----
            uint32_t a2[2][3][4];
            #pragma unroll
            for (int m = 0; m < 2; m++)
                #pragma unroll
                for (int t = 0; t < 3; t++) {
                    a2[m][t][0] = bfpk(d1[m][2 * t][1],     d1[m][2 * t][0]);
                    a2[m][t][1] = bfpk(d1[m][2 * t][3],     d1[m][2 * t][2]);
                    a2[m][t][2] = bfpk(d1[m][2 * t + 1][1], d1[m][2 * t + 1][0]);
                    a2[m][t][3] = bfpk(d1[m][2 * t + 1][3], d1[m][2 * t + 1][2]);
                }

            // ---- GEMM2: G[32px x 56n] = A2[32x48] * B2[48x56] ----
            float d2[2][7][4];
            #pragma unroll
            for (int m = 0; m < 2; m++)
                #pragma unroll
                for (int n = 0; n < 7; n++)
                    #pragma unroll
                    for (int e = 0; e < 4; e++) d2[m][n][e] = 0.f;
            #pragma unroll
            for (int k = 0; k < 3; k++) {
                #pragma unroll
                for (int n = 0; n < 7; n++) {
                    const char* bb = smem + B2_OFF + (n * 8 + g) * 144 + (k * 16 + tg * 2) * 2;
                    uint32_t b0 = *(const uint32_t*)bb;
                    uint32_t b1 = *(const uint32_t*)(bb + 16);
                    mma_bf16(d2[0][n], a2[0][k], b0, b1);
                    mma_bf16(d2[1][n], a2[1][k], b0, b1);
                }
            }

            // ---- store G ring (bf16, px stride 116B, ring & 15) ----
            char* grow = smem + G_OFF + (ra & 15) * GROWR;
            #pragma unroll
            for (int m = 0; m < 2; m++) {
                int pxA = ca0 + m * 16 + g;
                #pragma unroll
                for (int n = 0; n < 7; n++) {
                    uint32_t lo = bfpk(d2[m][n][1], d2[m][n][0]);
                    uint32_t hi = bfpk(d2[m][n][3], d2[m][n][2]);
                    int noff = (n * 8 + tg * 2) * 2;
                    *(uint32_t*)(grow + pxA * 116 + noff) = lo;
                    *(uint32_t*)(grow + (pxA + 8) * 116 + noff) = hi;
                }
            }
        }

        // ---- gather: col2im + residual for out rows 4(s-3)..4(s-3)+3 ----
        if (s >= 3) {
            int yl = 4 * (s - 3) + yh;
            int xg = x0 + xl;
            if (xl < 58 && xg < IMG) {
                float cv = 0.f;
                #pragma unroll
                for (int p = 0; p < 7; p++) {
                    const char* rb = smem + G_OFF + ((yl + 6 - p) & 15) * GROWR + p * 16;
                    #pragma unroll
                    for (int q = 0; q < 7; q++) {
                        uint16_t gv = *(const uint16_t*)(rb + (xl + 6 - q) * 116 + q * 2);
                        cv += __uint_as_float((uint32_t)gv << 16);
                    }
                }
                int yg = y0 + yl;
                float iv = ibase[yg * IMG + xg];
                float nv = nbase[yg * IMG + xg];
                float rv = iv - cv - nv;
                g_r[img * IMG * IMG + yg * IMG + xg] = rv;
                ss += rv * rv;
            }
        }
    }

    __syncthreads();
    float* red = (float*)(smem + RED_OFF);
    #pragma unroll
    for (int o = 16; o > 0; o >>= 1) ss += __shfl_down_sync(0xffffffffu, ss, o);
    if (lane == 0) red[wid] = ss;
    __syncthreads();
    if (tid == 0) {
        float t = 0.f;
        #pragma unroll
        for (int w = 0; w < 8; w++) t += red[w];
        g_partial[img * 20 + rr] = t;
    }
}

// ---------------- K3: scale + out = net_input + r*scale ----------------
__global__ void final_kernel(const float* __restrict__ net_input,
                             const float* __restrict__ stdn,
                             const float* __restrict__ alpha,
                             float* __restrict__ out) {
    __shared__ float sc_sh;
    int v = blockIdx.x * blockDim.x + threadIdx.x;  // float4 index
    int b = v >> 14;
    if (threadIdx.x == 0) {
        float s = 0.f;
        #pragma unroll
        for (int t = 0; t < 20; t++) s += g_partial[b * 20 + t];
        float nr = sqrtf(s);
        float k = expf(alpha[0]) * stdn[b] * 256.f;
        sc_sh = fminf(1.f, k / (nr + 1e-12f));
    }
    __syncthreads();
    float sc = sc_sh;
    float4 rr = ((const float4*)g_r)[v];
    float4 nn = ((const float4*)net_input)[v];
    float4 o;
    o.x = nn.x + rr.x * sc;
    o.y = nn.y + rr.y * sc;
    o.z = nn.z + rr.z * sc;
    o.w = nn.w + rr.w * sc;
    ((float4*)out)[v] = o;
}

extern "C" void kernel_launch(void* const* d_in, const int* in_sizes, int n_in,
                              void* d_out, int out_size) {
    const float* input     = (const float*)d_in[0];
    const float* stdn      = (const float*)d_in[1];
    const float* net_input = (const float*)d_in[3];
    const float* cw        = (const float*)d_in[4];
    const float* sf        = (const float*)d_in[5];
    const float* alpha     = (const float*)d_in[6];
    const float* rbw       = (const float*)d_in[7];
    const float* rbc       = (const float*)d_in[8];
    float* out = (float*)d_out;

    cudaFuncSetAttribute(main_kernel, cudaFuncAttributeMaxDynamicSharedMemorySize, SMEM_TOTAL);

    prep_kernel<<<NF, 256>>>(cw, sf, rbw, rbc);
    main_kernel<<<320, 256, SMEM_TOTAL>>>(input, net_input);
    final_kernel<<<1024, 256>>>(net_input, stdn, alpha, out);
}

// round 10
// speedup vs baseline: 3.4856x; 1.1395x over previous
#include <cuda_runtime.h>
#include <cuda_bf16.h>
#include <math.h>
#include <stdint.h>

#define NF   48
#define NM   51
#define IMG  256
#define TABN 2049

// ---- dynamic smem layout (bytes) ----
#define XCPY   10944            // one shifted x copy: 76 rows * 72 halves * 2B
#define B1_OFF 21888            // 48 rows * 144B = 6912
#define B2_OFF 28800            // 56 rows * 144B = 8064
#define G_OFF  36864            // ring: 16 * GROWR = 118784
#define GROWR  7424             // 64 px * 116B
#define RED_OFF 155648
#define SMEM_TOTAL 155776

// ---- device scratch ----
__device__ __align__(16) __nv_bfloat16 g_B1[NF * 64];   // [f][k=p*8+q]
__device__ __align__(16) __nv_bfloat16 g_B2[64 * 64];   // [n=p*8+q][f] (f>=48 zero)
__device__ float2 g_tab[NF * TABN];
__device__ float  g_r[16 * IMG * IMG];
__device__ float  g_partial[16 * 20];

__device__ __forceinline__ void mma_bf16(float c[4], const uint32_t a[4],
                                         uint32_t b0, uint32_t b1) {
    asm volatile("mma.sync.aligned.m16n8k16.row.col.f32.bf16.bf16.f32 "
        "{%0,%1,%2,%3}, {%4,%5,%6,%7}, {%8,%9}, {%0,%1,%2,%3};"
        : "+f"(c[0]), "+f"(c[1]), "+f"(c[2]), "+f"(c[3])
        : "r"(a[0]), "r"(a[1]), "r"(a[2]), "r"(a[3]), "r"(b0), "r"(b1));
}
__device__ __forceinline__ uint32_t bfpk(float hi, float lo) {
    uint32_t r; asm("cvt.rn.bf16x2.f32 %0, %1, %2;" : "=r"(r) : "f"(hi), "f"(lo)); return r;
}

// ---------------- K1: normalize weights -> B1/B2 bf16 + RBF tables ----------------
__global__ void prep_kernel(const float* __restrict__ cw, const float* __restrict__ sf,
                            const float* __restrict__ rbw, const float* __restrict__ rbc) {
    __shared__ float wn[49];
    __shared__ float msh[2];
    __shared__ float wsh[NM], csh[NM];
    __shared__ float tsh[TABN];
    int f = blockIdx.x, tid = threadIdx.x;

    if (tid < 49) wn[tid] = cw[f * 49 + tid];
    if (tid < NM) { wsh[tid] = rbw[f * NM + tid]; csh[tid] = rbc[tid]; }
    __syncthreads();
    if (tid == 0) {
        float mean = 0.f;
        #pragma unroll
        for (int i = 0; i < 49; i++) mean += wn[i];
        mean *= (1.f / 49.f);
        float ssq = 0.f;
        #pragma unroll
        for (int i = 0; i < 49; i++) { float d = wn[i] - mean; ssq += d * d; }
        msh[0] = mean;
        msh[1] = sf[f] / (sqrtf(ssq) + 1e-12f);
    }
    __syncthreads();
    if (tid < 49) wn[tid] = (wn[tid] - msh[0]) * msh[1];
    __syncthreads();
    if (tid < 64) {
        int p = tid >> 3, q = tid & 7;
        float v = (p < 7 && q < 7) ? wn[p * 7 + q] : 0.f;
        g_B1[f * 64 + tid] = __float2bfloat16(v);   // [f][k]
        g_B2[tid * 64 + f] = __float2bfloat16(v);   // [n][f]
    }
    for (int k = tid; k < TABN; k += blockDim.x) {
        float z = -16.f + (float)k * (1.f / 64.f);
        float acc = 0.f;
        #pragma unroll
        for (int m = 0; m < NM; m++) {
            float d = z - csh[m];
            acc += wsh[m] * __expf(-0.01f * d * d);
        }
        tsh[k] = acc;
    }
    __syncthreads();
    for (int k = tid; k < TABN; k += blockDim.x) {
        float v = tsh[k];
        float dl = (k < TABN - 1) ? (tsh[k + 1] - v) : 0.f;
        g_tab[f * TABN + k] = make_float2(v, dl);
    }
}

// ---------------- K2: fused tensor-core main (mma.sync, 16 worker warps) ----------------
// grid 320 = 16 img x 4 ytiles x 5 xtiles; 512 threads
__global__ void __launch_bounds__(512)
main_kernel(const float* __restrict__ input, const float* __restrict__ net_input) {
    extern __shared__ __align__(16) char smem[];

    int bid = blockIdx.x;
    int img = bid / 20;
    int rr  = bid % 20;
    int y0 = (rr / 5) * 64;
    int x0 = (rr % 5) * 58;
    int tid  = threadIdx.x;
    int wid  = tid >> 5;
    int lane = tid & 31;

    const float* ibase = input + img * IMG * IMG;
    const float* nbase = net_input + img * IMG * IMG;

    // ---- stage x halo: 2 shifted bf16 copies (76 rows x 71 cols) ----
    __nv_bfloat16* xs0 = (__nv_bfloat16*)smem;
    __nv_bfloat16* xs1 = (__nv_bfloat16*)(smem + XCPY);
    for (int idx = tid; idx < 76 * 71; idx += 512) {
        int xr = idx / 71, xc = idx - xr * 71;
        int gy = y0 - 6 + xr, gx = x0 - 6 + xc;
        gy = (gy < 0) ? (-1 - gy) : ((gy >= IMG) ? (2 * IMG - 1 - gy) : gy);
        gx = (gx < 0) ? (-1 - gx) : ((gx >= IMG) ? (2 * IMG - 1 - gx) : gx);
        __nv_bfloat16 v = __float2bfloat16(ibase[gy * IMG + gx]);
        xs0[xr * 72 + xc] = v;
        if (xc >= 1) xs1[xr * 72 + xc - 1] = v;
    }
    // ---- stage B1 (48x64) and B2 (56x64), row stride 144B ----
    for (int i = tid; i < 48 * 8; i += 512) {
        int r = i >> 3, cj = i & 7;
        *(uint4*)(smem + B1_OFF + r * 144 + cj * 16) = *(const uint4*)(g_B1 + r * 64 + cj * 8);
    }
    for (int i = tid; i < 56 * 8; i += 512) {
        int r = i >> 3, cj = i & 7;
        *(uint4*)(smem + B2_OFF + r * 144 + cj * 16) = *(const uint4*)(g_B2 + r * 64 + cj * 8);
    }
    __syncthreads();

    int g  = lane >> 2;       // 0..7
    int tg = lane & 3;        // 0..3
    float ss = 0.f;

    // worker constants
    int ca0  = (wid & 1) * 32;
    int roct = wid >> 1;                 // 0..7
    const char* xc = smem + (g & 1) * XCPY;
    int colb = ca0 + 2 * tg + g - (g & 1);   // + m*16 per m, in halves

    // gather constants
    int xl = tid & 63;
    int yh = tid >> 6;                   // 0..7

    #pragma unroll 1
    for (int s = 0; s < 9; s++) {
        __syncthreads();   // ring-slot reuse safety (prev gathers done)

        int ra = 8 * s + roct;
        if (ra < 70) {
            // ---- GEMM1: D1[32px x 48f], A frags direct from x copies ----
            float d1[2][6][4];
            #pragma unroll
            for (int m = 0; m < 2; m++)
                #pragma unroll
                for (int n = 0; n < 6; n++)
                    #pragma unroll
                    for (int e = 0; e < 4; e++) d1[m][n][e] = 0.f;
            #pragma unroll
            for (int k = 0; k < 4; k++) {
                uint32_t afr[2][4];
                #pragma unroll
                for (int m = 0; m < 2; m++) {
                    const char* ab = xc + (((ra + 2 * k) * 72) + colb + m * 16) * 2;
                    afr[m][0] = *(const uint32_t*)ab;
                    afr[m][1] = *(const uint32_t*)(ab + 16);
                    if (k < 3) {
                        afr[m][2] = *(const uint32_t*)(ab + 144);
                        afr[m][3] = *(const uint32_t*)(ab + 160);
                    } else {
                        afr[m][2] = 0u; afr[m][3] = 0u;   // k>=56 hits zero B cols
                    }
                }
                #pragma unroll
                for (int n = 0; n < 6; n++) {
                    const char* bb = smem + B1_OFF + (n * 8 + g) * 144 + (k * 16 + tg * 2) * 2;
                    uint32_t b0 = *(const uint32_t*)bb;
                    uint32_t b1 = *(const uint32_t*)(bb + 16);
                    mma_bf16(d1[0][n], afr[0], b0, b1);
                    mma_bf16(d1[1][n], afr[1], b0, b1);
                }
            }

            // ---- RBF lerp in-register (+ zero outside image) ----
            int u = y0 - 3 + ra;
            bool uok = (u >= 0) && (u < IMG);
            #pragma unroll
            for (int m = 0; m < 2; m++) {
                int vA = x0 - 3 + ca0 + m * 16 + g;
                int vB = vA + 8;
                bool okA = uok && (vA >= 0) && (vA < IMG);
                bool okB = uok && (vB >= 0) && (vB < IMG);
                #pragma unroll
                for (int n = 0; n < 6; n++) {
                    #pragma unroll
                    for (int e = 0; e < 4; e++) {
                        bool ok = (e < 2) ? okA : okB;
                        int fidx = n * 8 + tg * 2 + (e & 1);
                        float z = d1[m][n][e];
                        float t = fminf(fmaxf((z + 16.f) * 64.f, 0.f), 2047.99f);
                        int ix = (int)t;
                        float fr = t - (float)ix;
                        float2 tv = __ldg(&g_tab[fidx * TABN + ix]);
                        float a = tv.x + fr * tv.y;
                        d1[m][n][e] = ok ? a : 0.f;
                    }
                }
            }

            // ---- repack D1 -> A fragments of GEMM2 (register-only) ----
            uint32_t a2[2][3][4];
            #pragma unroll
            for (int m = 0; m < 2; m++)
                #pragma unroll
                for (int t = 0; t < 3; t++) {
                    a2[m][t][0] = bfpk(d1[m][2 * t][1],     d1[m][2 * t][0]);
                    a2[m][t][1] = bfpk(d1[m][2 * t][3],     d1[m][2 * t][2]);
                    a2[m][t][2] = bfpk(d1[m][2 * t + 1][1], d1[m][2 * t + 1][0]);
                    a2[m][t][3] = bfpk(d1[m][2 * t + 1][3], d1[m][2 * t + 1][2]);
                }

            // ---- GEMM2: G[32px x 56n] = A2[32x48] * B2[48x56] ----
            float d2[2][7][4];
            #pragma unroll
            for (int m = 0; m < 2; m++)
                #pragma unroll
                for (int n = 0; n < 7; n++)
                    #pragma unroll
                    for (int e = 0; e < 4; e++) d2[m][n][e] = 0.f;
            #pragma unroll
            for (int k = 0; k < 3; k++) {
                #pragma unroll
                for (int n = 0; n < 7; n++) {
                    const char* bb = smem + B2_OFF + (n * 8 + g) * 144 + (k * 16 + tg * 2) * 2;
                    uint32_t b0 = *(const uint32_t*)bb;
                    uint32_t b1 = *(const uint32_t*)(bb + 16);
                    mma_bf16(d2[0][n], a2[0][k], b0, b1);
                    mma_bf16(d2[1][n], a2[1][k], b0, b1);
                }
            }

            // ---- store G ring (bf16, px stride 116B, ring & 15) ----
            char* grow = smem + G_OFF + (ra & 15) * GROWR;
            #pragma unroll
            for (int m = 0; m < 2; m++) {
                int pxA = ca0 + m * 16 + g;
                #pragma unroll
                for (int n = 0; n < 7; n++) {
                    uint32_t lo = bfpk(d2[m][n][1], d2[m][n][0]);
                    uint32_t hi = bfpk(d2[m][n][3], d2[m][n][2]);
                    int noff = (n * 8 + tg * 2) * 2;
                    *(uint32_t*)(grow + pxA * 116 + noff) = lo;
                    *(uint32_t*)(grow + (pxA + 8) * 116 + noff) = hi;
                }
            }
        }

        __syncthreads();   // G for this slab complete

        // ---- gather: col2im + residual for out rows 8(s-1)..8(s-1)+7 ----
        if (s >= 1) {
            int yl = 8 * (s - 1) + yh;
            int xg = x0 + xl;
            if (xl < 58 && xg < IMG) {
                float cv = 0.f;
                #pragma unroll
                for (int p = 0; p < 7; p++) {
                    const char* rb = smem + G_OFF + ((yl + 6 - p) & 15) * GROWR + p * 16;
                    #pragma unroll
                    for (int q = 0; q < 7; q++) {
                        uint16_t gv = *(const uint16_t*)(rb + (xl + 6 - q) * 116 + q * 2);
                        cv += __uint_as_float((uint32_t)gv << 16);
                    }
                }
                int yg = y0 + yl;
                float iv = ibase[yg * IMG + xg];
                float nv = nbase[yg * IMG + xg];
                float rv = iv - cv - nv;
                g_r[img * IMG * IMG + yg * IMG + xg] = rv;
                ss += rv * rv;
            }
        }
    }

    __syncthreads();
    float* red = (float*)(smem + RED_OFF);
    #pragma unroll
    for (int o = 16; o > 0; o >>= 1) ss += __shfl_down_sync(0xffffffffu, ss, o);
    if (lane == 0) red[wid] = ss;
    __syncthreads();
    if (tid == 0) {
        float t = 0.f;
        #pragma unroll
        for (int w = 0; w < 16; w++) t += red[w];
        g_partial[img * 20 + rr] = t;
    }
}

// ---------------- K3: scale + out = net_input + r*scale ----------------
__global__ void final_kernel(const float* __restrict__ net_input,
                             const float* __restrict__ stdn,
                             const float* __restrict__ alpha,
                             float* __restrict__ out) {
    __shared__ float sc_sh;
    int v = blockIdx.x * blockDim.x + threadIdx.x;  // float4 index
    int b = v >> 14;
    if (threadIdx.x == 0) {
        float s = 0.f;
        #pragma unroll
        for (int t = 0; t < 20; t++) s += g_partial[b * 20 + t];
        float nr = sqrtf(s);
        float k = expf(alpha[0]) * stdn[b] * 256.f;
        sc_sh = fminf(1.f, k / (nr + 1e-12f));
    }
    __syncthreads();
    float sc = sc_sh;
    float4 rr = ((const float4*)g_r)[v];
    float4 nn = ((const float4*)net_input)[v];
    float4 o;
    o.x = nn.x + rr.x * sc;
    o.y = nn.y + rr.y * sc;
    o.z = nn.z + rr.z * sc;
    o.w = nn.w + rr.w * sc;
    ((float4*)out)[v] = o;
}

extern "C" void kernel_launch(void* const* d_in, const int* in_sizes, int n_in,
                              void* d_out, int out_size) {
    const float* input     = (const float*)d_in[0];
    const float* stdn      = (const float*)d_in[1];
    const float* net_input = (const float*)d_in[3];
    const float* cw        = (const float*)d_in[4];
    const float* sf        = (const float*)d_in[5];
    const float* alpha     = (const float*)d_in[6];
    const float* rbw       = (const float*)d_in[7];
    const float* rbc       = (const float*)d_in[8];
    float* out = (float*)d_out;

    cudaFuncSetAttribute(main_kernel, cudaFuncAttributeMaxDynamicSharedMemorySize, SMEM_TOTAL);

    prep_kernel<<<NF, 256>>>(cw, sf, rbw, rbc);
    main_kernel<<<320, 512, SMEM_TOTAL>>>(input, net_input);
    final_kernel<<<1024, 256>>>(net_input, stdn, alpha, out);
}